// round 6
// baseline (speedup 1.0000x reference)
#include <cuda_runtime.h>

#define N_SAMPLES 128
#define FULL 0xFFFFFFFFu
#define THREADS 256
#define BLOCKS 1184   // 148 SMs x 8 CTAs/SM -> single persistent wave

__global__ void __launch_bounds__(THREADS) raymarch_kernel(
    const float* __restrict__ sigma,   // [N, 128]
    const float* __restrict__ rgb,     // [N, 128, 3]
    const float* __restrict__ dists,   // [N, 128]
    const float* __restrict__ z_vals,  // [N, 128]
    const float* __restrict__ bg,      // [N, 3]
    float* __restrict__ out,           // [N, 4]
    int n_rays)
{
    const int lane      = threadIdx.x & 31;
    const int warp0     = (blockIdx.x * THREADS + threadIdx.x) >> 5;
    const int n_warps   = (gridDim.x * THREADS) >> 5;   // total warps in grid

    for (long ray = warp0; ray < n_rays; ray += n_warps) {
        const long base = ray * N_SAMPLES + lane * 4;   // 4 consecutive samples/lane

        // ---- issue all global loads up front (high MLP) ----
        const float4 s4 = __ldcs(reinterpret_cast<const float4*>(sigma  + base));
        const float4 d4 = __ldcs(reinterpret_cast<const float4*>(dists  + base));
        const float4 z4 = __ldcs(reinterpret_cast<const float4*>(z_vals + base));

        const float4* rgb4 = reinterpret_cast<const float4*>(rgb + ray * (N_SAMPLES * 3) + lane * 12);
        const float4 c0 = __ldcs(rgb4 + 0);   // r0 g0 b0 r1
        const float4 c1 = __ldcs(rgb4 + 1);   // g1 b1 r2 g2
        const float4 c2 = __ldcs(rgb4 + 2);   // b2 r3 g3 b3

        // ---- alpha + per-lane transmittance factors ----
        float sig[4] = {s4.x, s4.y, s4.z, s4.w};
        float dst[4] = {d4.x, d4.y, d4.z, d4.w};
        float zz[4]  = {z4.x, z4.y, z4.z, z4.w};

        float alpha[4], g[4];
        #pragma unroll
        for (int i = 0; i < 4; i++) {
            float tau = fmaxf(sig[i], 0.0f) * dst[i];
            alpha[i]  = 1.0f - __expf(-tau);
            g[i]      = 1.0f - alpha[i] + 1e-10f;
        }

        // ---- multiplicative inclusive warp scan of per-lane products ----
        float scan = g[0] * g[1] * g[2] * g[3];
        #pragma unroll
        for (int d = 1; d < 32; d <<= 1) {
            float t = __shfl_up_sync(FULL, scan, d);
            if (lane >= d) scan *= t;
        }
        float T = __shfl_up_sync(FULL, scan, 1);      // exclusive prefix
        if (lane == 0) T = 1.0f;
        const float no_hit = __shfl_sync(FULL, scan, 31);  // full product

        // ---- sequential composite of the 4 owned samples ----
        float rr[4] = {c0.x, c0.w, c1.z, c2.y};
        float gg[4] = {c0.y, c1.x, c1.w, c2.z};
        float bb[4] = {c0.z, c1.y, c2.x, c2.w};

        float cr = 0.f, cg = 0.f, cb = 0.f, depth = 0.f;
        #pragma unroll
        for (int i = 0; i < 4; i++) {
            float w = alpha[i] * T;
            cr    = fmaf(w, rr[i], cr);
            cg    = fmaf(w, gg[i], cg);
            cb    = fmaf(w, bb[i], cb);
            depth = fmaf(w, zz[i], depth);
            T *= g[i];
        }

        // ---- warp reductions ----
        #pragma unroll
        for (int off = 16; off >= 1; off >>= 1) {
            cr    += __shfl_xor_sync(FULL, cr,    off);
            cg    += __shfl_xor_sync(FULL, cg,    off);
            cb    += __shfl_xor_sync(FULL, cb,    off);
            depth += __shfl_xor_sync(FULL, depth, off);
        }

        if (lane == 0) {
            const float bgx = __ldcs(bg + ray * 3 + 0);
            const float bgy = __ldcs(bg + ray * 3 + 1);
            const float bgz = __ldcs(bg + ray * 3 + 2);
            float4 o;
            o.x = fmaf(no_hit, bgx, cr);
            o.y = fmaf(no_hit, bgy, cg);
            o.z = fmaf(no_hit, bgz, cb);
            o.w = depth;
            *reinterpret_cast<float4*>(out + ray * 4) = o;
        }
    }
}

extern "C" void kernel_launch(void* const* d_in, const int* in_sizes, int n_in,
                              void* d_out, int out_size)
{
    const float* sigma  = (const float*)d_in[0];
    const float* rgb    = (const float*)d_in[1];
    const float* dists  = (const float*)d_in[2];
    const float* z_vals = (const float*)d_in[3];
    const float* bg     = (const float*)d_in[4];
    float* out = (float*)d_out;

    const int n_rays = in_sizes[0] / N_SAMPLES;   // 65536

    raymarch_kernel<<<BLOCKS, THREADS>>>(sigma, rgb, dists, z_vals, bg, out, n_rays);
}

// round 7
// speedup vs baseline: 1.1145x; 1.1145x over previous
#include <cuda_runtime.h>

#define N_SAMPLES 128
#define FULL 0xFFFFFFFFu

__global__ void __launch_bounds__(256) raymarch_kernel(
    const float* __restrict__ sigma,   // [N, 128]
    const float* __restrict__ rgb,     // [N, 128, 3]
    const float* __restrict__ dists,   // [N, 128]
    const float* __restrict__ z_vals,  // [N, 128]
    const float* __restrict__ bg,      // [N, 3]
    float* __restrict__ out,           // [N, 4]
    int n_rays)
{
    const int warp_id = (blockIdx.x * blockDim.x + threadIdx.x) >> 5;
    const int lane    = threadIdx.x & 31;
    if (warp_id >= n_rays) return;

    const long ray  = warp_id;
    const long base = ray * N_SAMPLES + lane * 4;   // 4 consecutive samples per lane

    // ---- coalesced streaming vector loads (all issued up front) ----
    const float4 s4 = __ldcs(reinterpret_cast<const float4*>(sigma  + base));
    const float4 d4 = __ldcs(reinterpret_cast<const float4*>(dists  + base));
    const float4 z4 = __ldcs(reinterpret_cast<const float4*>(z_vals + base));

    const float4* rgb4 = reinterpret_cast<const float4*>(rgb + ray * (N_SAMPLES * 3) + lane * 12);
    const float4 c0 = __ldcs(rgb4 + 0);   // r0 g0 b0 r1
    const float4 c1 = __ldcs(rgb4 + 1);   // g1 b1 r2 g2
    const float4 c2 = __ldcs(rgb4 + 2);   // b2 r3 g3 b3

    // ---- alpha + per-lane factors ----
    float sig[4] = {s4.x, s4.y, s4.z, s4.w};
    float dst[4] = {d4.x, d4.y, d4.z, d4.w};
    float zz[4]  = {z4.x, z4.y, z4.z, z4.w};

    float alpha[4], g[4];
    #pragma unroll
    for (int i = 0; i < 4; i++) {
        float tau = fmaxf(sig[i], 0.0f) * dst[i];
        alpha[i]  = 1.0f - __expf(-tau);
        g[i]      = 1.0f - alpha[i] + 1e-10f;
    }

    // ---- multiplicative inclusive warp scan of per-lane products ----
    float scan = g[0] * g[1] * g[2] * g[3];
    #pragma unroll
    for (int d = 1; d < 32; d <<= 1) {
        float t = __shfl_up_sync(FULL, scan, d);
        if (lane >= d) scan *= t;
    }
    // exclusive prefix for this lane
    float T = __shfl_up_sync(FULL, scan, 1);
    if (lane == 0) T = 1.0f;
    // full product (transmittance after all samples) lives at lane 31
    const float no_hit = __shfl_sync(FULL, scan, 31);

    // ---- sequential composite of the 4 owned samples ----
    float rr[4] = {c0.x, c0.w, c1.z, c2.y};
    float gg[4] = {c0.y, c1.x, c1.w, c2.z};
    float bb[4] = {c0.z, c1.y, c2.x, c2.w};

    float cr = 0.f, cg = 0.f, cb = 0.f, depth = 0.f;
    #pragma unroll
    for (int i = 0; i < 4; i++) {
        float w = alpha[i] * T;
        cr    = fmaf(w, rr[i], cr);
        cg    = fmaf(w, gg[i], cg);
        cb    = fmaf(w, bb[i], cb);
        depth = fmaf(w, zz[i], depth);
        T *= g[i];
    }

    // ---- warp reductions ----
    #pragma unroll
    for (int off = 16; off >= 1; off >>= 1) {
        cr    += __shfl_xor_sync(FULL, cr,    off);
        cg    += __shfl_xor_sync(FULL, cg,    off);
        cb    += __shfl_xor_sync(FULL, cb,    off);
        depth += __shfl_xor_sync(FULL, depth, off);
    }

    if (lane == 0) {
        const float bgx = __ldg(bg + ray * 3 + 0);
        const float bgy = __ldg(bg + ray * 3 + 1);
        const float bgz = __ldg(bg + ray * 3 + 2);
        float4 o;
        o.x = fmaf(no_hit, bgx, cr);
        o.y = fmaf(no_hit, bgy, cg);
        o.z = fmaf(no_hit, bgz, cb);
        o.w = depth;
        *reinterpret_cast<float4*>(out + ray * 4) = o;
    }
}

extern "C" void kernel_launch(void* const* d_in, const int* in_sizes, int n_in,
                              void* d_out, int out_size)
{
    const float* sigma  = (const float*)d_in[0];
    const float* rgb    = (const float*)d_in[1];
    const float* dists  = (const float*)d_in[2];
    const float* z_vals = (const float*)d_in[3];
    const float* bg     = (const float*)d_in[4];
    float* out = (float*)d_out;

    const int n_rays = in_sizes[0] / N_SAMPLES;   // 65536

    const int threads = 256;                 // 8 warps = 8 rays per block
    const int rays_per_block = threads / 32;
    const int blocks = (n_rays + rays_per_block - 1) / rays_per_block;
    raymarch_kernel<<<blocks, threads>>>(sigma, rgb, dists, z_vals, bg, out, n_rays);
}

// round 9
// speedup vs baseline: 1.1231x; 1.0077x over previous
#include <cuda_runtime.h>

#define N_SAMPLES 128
#define FULL 0xFFFFFFFFu
#define THREADS 128   // 4 warps/block -> 16 CTAs/SM at 32 regs; smoother L1tex queue

__global__ void __launch_bounds__(THREADS) raymarch_kernel(
    const float* __restrict__ sigma,   // [N, 128]
    const float* __restrict__ rgb,     // [N, 128, 3]
    const float* __restrict__ dists,   // [N, 128]
    const float* __restrict__ z_vals,  // [N, 128]
    const float* __restrict__ bg,      // [N, 3]
    float* __restrict__ out,           // [N, 4]
    int n_rays)
{
    const int warp_id = (blockIdx.x * blockDim.x + threadIdx.x) >> 5;
    const int lane    = threadIdx.x & 31;
    if (warp_id >= n_rays) return;

    const long ray  = warp_id;
    const long base = ray * N_SAMPLES + lane * 4;   // 4 consecutive samples per lane

    // ---- coalesced streaming vector loads (all issued up front) ----
    const float4 s4 = __ldcs(reinterpret_cast<const float4*>(sigma  + base));
    const float4 d4 = __ldcs(reinterpret_cast<const float4*>(dists  + base));
    const float4 z4 = __ldcs(reinterpret_cast<const float4*>(z_vals + base));

    const float4* rgb4 = reinterpret_cast<const float4*>(rgb + ray * (N_SAMPLES * 3) + lane * 12);
    const float4 c0 = __ldcs(rgb4 + 0);   // r0 g0 b0 r1
    const float4 c1 = __ldcs(rgb4 + 1);   // g1 b1 r2 g2
    const float4 c2 = __ldcs(rgb4 + 2);   // b2 r3 g3 b3

    // ---- alpha + per-lane factors ----
    // e = exp(-relu(sigma)*dist);  alpha = 1-e;  g = (1-alpha)+eps = e+eps
    float sig[4] = {s4.x, s4.y, s4.z, s4.w};
    float dst[4] = {d4.x, d4.y, d4.z, d4.w};
    float zz[4]  = {z4.x, z4.y, z4.z, z4.w};

    float alpha[4], g[4];
    #pragma unroll
    for (int i = 0; i < 4; i++) {
        float tau = fmaxf(sig[i], 0.0f) * dst[i];
        float e   = __expf(-tau);
        alpha[i]  = 1.0f - e;
        g[i]      = e + 1e-10f;
    }

    // ---- multiplicative inclusive warp scan of per-lane products ----
    float scan = (g[0] * g[1]) * (g[2] * g[3]);
    #pragma unroll
    for (int d = 1; d < 32; d <<= 1) {
        float t = __shfl_up_sync(FULL, scan, d);
        if (lane >= d) scan *= t;
    }
    // exclusive prefix for this lane
    float T = __shfl_up_sync(FULL, scan, 1);
    if (lane == 0) T = 1.0f;
    // full product (transmittance after all samples) lives at lane 31
    const float no_hit = __shfl_sync(FULL, scan, 31);

    // ---- sequential composite of the 4 owned samples ----
    float rr[4] = {c0.x, c0.w, c1.z, c2.y};
    float gg[4] = {c0.y, c1.x, c1.w, c2.z};
    float bb[4] = {c0.z, c1.y, c2.x, c2.w};

    float cr = 0.f, cg = 0.f, cb = 0.f, depth = 0.f;
    #pragma unroll
    for (int i = 0; i < 4; i++) {
        float w = alpha[i] * T;
        cr    = fmaf(w, rr[i], cr);
        cg    = fmaf(w, gg[i], cg);
        cb    = fmaf(w, bb[i], cb);
        depth = fmaf(w, zz[i], depth);
        T *= g[i];
    }

    // ---- warp reductions ----
    #pragma unroll
    for (int off = 16; off >= 1; off >>= 1) {
        cr    += __shfl_xor_sync(FULL, cr,    off);
        cg    += __shfl_xor_sync(FULL, cg,    off);
        cb    += __shfl_xor_sync(FULL, cb,    off);
        depth += __shfl_xor_sync(FULL, depth, off);
    }

    if (lane == 0) {
        const float bgx = __ldg(bg + ray * 3 + 0);
        const float bgy = __ldg(bg + ray * 3 + 1);
        const float bgz = __ldg(bg + ray * 3 + 2);
        float4 o;
        o.x = fmaf(no_hit, bgx, cr);
        o.y = fmaf(no_hit, bgy, cg);
        o.z = fmaf(no_hit, bgz, cb);
        o.w = depth;
        __stwt(reinterpret_cast<float4*>(out + ray * 4), o);
    }
}

extern "C" void kernel_launch(void* const* d_in, const int* in_sizes, int n_in,
                              void* d_out, int out_size)
{
    const float* sigma  = (const float*)d_in[0];
    const float* rgb    = (const float*)d_in[1];
    const float* dists  = (const float*)d_in[2];
    const float* z_vals = (const float*)d_in[3];
    const float* bg     = (const float*)d_in[4];
    float* out = (float*)d_out;

    const int n_rays = in_sizes[0] / N_SAMPLES;   // 65536

    const int rays_per_block = THREADS / 32;
    const int blocks = (n_rays + rays_per_block - 1) / rays_per_block;
    raymarch_kernel<<<blocks, THREADS>>>(sigma, rgb, dists, z_vals, bg, out, n_rays);
}

// round 10
// speedup vs baseline: 1.1242x; 1.0010x over previous
#include <cuda_runtime.h>

#define N_SAMPLES 128
#define FULL 0xFFFFFFFFu
#define THREADS 64   // 2 warps/block -> 32 CTAs/SM, 64 warps/SM at 32 regs

__global__ void __launch_bounds__(THREADS) raymarch_kernel(
    const float* __restrict__ sigma,   // [N, 128]
    const float* __restrict__ rgb,     // [N, 128, 3]
    const float* __restrict__ dists,   // [N, 128]
    const float* __restrict__ z_vals,  // [N, 128]
    const float* __restrict__ bg,      // [N, 3]
    float* __restrict__ out,           // [N, 4]
    int n_rays)
{
    const int warp_id = (blockIdx.x * blockDim.x + threadIdx.x) >> 5;
    const int lane    = threadIdx.x & 31;
    if (warp_id >= n_rays) return;

    const long ray  = warp_id;
    const long base = ray * N_SAMPLES + lane * 4;   // 4 consecutive samples per lane

    // ---- issue heavy rgb loads first (longest L1 service), then scalars ----
    const float4* rgb4 = reinterpret_cast<const float4*>(rgb + ray * (N_SAMPLES * 3) + lane * 12);
    const float4 c0 = __ldcs(rgb4 + 0);   // r0 g0 b0 r1
    const float4 c1 = __ldcs(rgb4 + 1);   // g1 b1 r2 g2
    const float4 c2 = __ldcs(rgb4 + 2);   // b2 r3 g3 b3

    const float4 s4 = __ldcs(reinterpret_cast<const float4*>(sigma  + base));
    const float4 d4 = __ldcs(reinterpret_cast<const float4*>(dists  + base));
    const float4 z4 = __ldcs(reinterpret_cast<const float4*>(z_vals + base));

    // hoist bg load: overlap its latency with the whole compute phase
    float bgx = 0.f, bgy = 0.f, bgz = 0.f;
    if (lane == 0) {
        bgx = __ldg(bg + ray * 3 + 0);
        bgy = __ldg(bg + ray * 3 + 1);
        bgz = __ldg(bg + ray * 3 + 2);
    }

    // ---- alpha + per-lane factors ----
    // e = exp(-relu(sigma)*dist);  alpha = 1-e;  g = e+eps
    float sig[4] = {s4.x, s4.y, s4.z, s4.w};
    float dst[4] = {d4.x, d4.y, d4.z, d4.w};
    float zz[4]  = {z4.x, z4.y, z4.z, z4.w};

    float alpha[4], g[4];
    #pragma unroll
    for (int i = 0; i < 4; i++) {
        float tau = fmaxf(sig[i], 0.0f) * dst[i];
        float e   = __expf(-tau);
        alpha[i]  = 1.0f - e;
        g[i]      = e + 1e-10f;
    }

    // ---- multiplicative inclusive warp scan of per-lane products ----
    float scan = (g[0] * g[1]) * (g[2] * g[3]);
    #pragma unroll
    for (int d = 1; d < 32; d <<= 1) {
        float t = __shfl_up_sync(FULL, scan, d);
        if (lane >= d) scan *= t;
    }
    // exclusive prefix for this lane
    float T = __shfl_up_sync(FULL, scan, 1);
    if (lane == 0) T = 1.0f;
    // full product (transmittance after all samples) lives at lane 31
    const float no_hit = __shfl_sync(FULL, scan, 31);

    // ---- sequential composite of the 4 owned samples ----
    float rr[4] = {c0.x, c0.w, c1.z, c2.y};
    float gg[4] = {c0.y, c1.x, c1.w, c2.z};
    float bb[4] = {c0.z, c1.y, c2.x, c2.w};

    float cr = 0.f, cg = 0.f, cb = 0.f, depth = 0.f;
    #pragma unroll
    for (int i = 0; i < 4; i++) {
        float w = alpha[i] * T;
        cr    = fmaf(w, rr[i], cr);
        cg    = fmaf(w, gg[i], cg);
        cb    = fmaf(w, bb[i], cb);
        depth = fmaf(w, zz[i], depth);
        T *= g[i];
    }

    // ---- warp reductions ----
    #pragma unroll
    for (int off = 16; off >= 1; off >>= 1) {
        cr    += __shfl_xor_sync(FULL, cr,    off);
        cg    += __shfl_xor_sync(FULL, cg,    off);
        cb    += __shfl_xor_sync(FULL, cb,    off);
        depth += __shfl_xor_sync(FULL, depth, off);
    }

    if (lane == 0) {
        float4 o;
        o.x = fmaf(no_hit, bgx, cr);
        o.y = fmaf(no_hit, bgy, cg);
        o.z = fmaf(no_hit, bgz, cb);
        o.w = depth;
        __stwt(reinterpret_cast<float4*>(out + ray * 4), o);
    }
}

extern "C" void kernel_launch(void* const* d_in, const int* in_sizes, int n_in,
                              void* d_out, int out_size)
{
    const float* sigma  = (const float*)d_in[0];
    const float* rgb    = (const float*)d_in[1];
    const float* dists  = (const float*)d_in[2];
    const float* z_vals = (const float*)d_in[3];
    const float* bg     = (const float*)d_in[4];
    float* out = (float*)d_out;

    const int n_rays = in_sizes[0] / N_SAMPLES;   // 65536

    const int rays_per_block = THREADS / 32;
    const int blocks = (n_rays + rays_per_block - 1) / rays_per_block;
    raymarch_kernel<<<blocks, THREADS>>>(sigma, rgb, dists, z_vals, bg, out, n_rays);
}